// round 4
// baseline (speedup 1.0000x reference)
#include <cuda_runtime.h>
#include <math.h>

#define NSEQ 128
#define NRES 256
#define MSA_DIM 256
#define PAIR_DIM 128
#define NHEAD 8
#define HEAD_DIM 32
#define NROWS (NSEQ * NRES) /* 32768 */

// -------- scratch (device globals; no allocations allowed) --------
__device__ float g_x[NROWS * MSA_DIM];     // LN(msa_act)
__device__ float g_q[NROWS * MSA_DIM];     // q (scaled)
__device__ float g_k[NROWS * MSA_DIM];
__device__ float g_v[NROWS * MSA_DIM];
__device__ float g_g[NROWS * MSA_DIM];     // sigmoid gate
__device__ float g_wg[NROWS * MSA_DIM];    // weighted_avg * gate
__device__ float g_bias[NHEAD * NRES * NRES]; // nonbatched bias [h][q][k]

// ===================== 1) LayerNorm of msa_act =====================
__global__ __launch_bounds__(256) void ln_msa_kernel(
    const float* __restrict__ msa, const float* __restrict__ sc,
    const float* __restrict__ bi)
{
    int row = blockIdx.x;
    int t = threadIdx.x;
    float v = msa[row * 256 + t];
    float s = v, s2 = v * v;
#pragma unroll
    for (int o = 16; o; o >>= 1) {
        s  += __shfl_xor_sync(0xffffffffu, s, o);
        s2 += __shfl_xor_sync(0xffffffffu, s2, o);
    }
    __shared__ float ss[8], ss2[8];
    if ((t & 31) == 0) { ss[t >> 5] = s; ss2[t >> 5] = s2; }
    __syncthreads();
    float tot = 0.f, tot2 = 0.f;
#pragma unroll
    for (int i = 0; i < 8; i++) { tot += ss[i]; tot2 += ss2[i]; }
    float mu  = tot * (1.f / 256.f);
    float var = tot2 * (1.f / 256.f) - mu * mu;
    float r = rsqrtf(var + 1e-5f);
    g_x[row * 256 + t] = (v - mu) * r * sc[t] + bi[t];
}

// ===================== 2) pair LN + feat2d projection =====================
// one warp per (q,k) pair; bias[h][q][k] = sum_c LN(pair)[q,k,c] * f2w[c,h]
__global__ __launch_bounds__(256) void pair_bias_kernel(
    const float* __restrict__ pair, const float* __restrict__ psc,
    const float* __restrict__ pbi, const float* __restrict__ f2w)
{
    __shared__ float f2t[NHEAD * PAIR_DIM]; // transposed: [h][c]
    int tid = threadIdx.x;
    for (int i = tid; i < NHEAD * PAIR_DIM; i += 256) {
        int c = i >> 3, h = i & 7;
        f2t[h * PAIR_DIM + c] = f2w[i];
    }
    __syncthreads();

    int pid = blockIdx.x * 8 + (tid >> 5); // pair index q*256+k
    int lane = tid & 31;

    const float* row = pair + pid * PAIR_DIM;
    float4 v = *(const float4*)(row + lane * 4);
    float s = v.x + v.y + v.z + v.w;
    float s2 = v.x * v.x + v.y * v.y + v.z * v.z + v.w * v.w;
#pragma unroll
    for (int o = 16; o; o >>= 1) {
        s  += __shfl_xor_sync(0xffffffffu, s, o);
        s2 += __shfl_xor_sync(0xffffffffu, s2, o);
    }
    float mu  = s * (1.f / 128.f);
    float var = s2 * (1.f / 128.f) - mu * mu;
    float r = rsqrtf(var + 1e-5f);

    float4 sc = *(const float4*)(psc + lane * 4);
    float4 bb = *(const float4*)(pbi + lane * 4);
    float x0 = (v.x - mu) * r * sc.x + bb.x;
    float x1 = (v.y - mu) * r * sc.y + bb.y;
    float x2 = (v.z - mu) * r * sc.z + bb.z;
    float x3 = (v.w - mu) * r * sc.w + bb.w;

#pragma unroll
    for (int h = 0; h < 8; h++) {
        const float4 w = *(const float4*)&f2t[h * PAIR_DIM + lane * 4];
        float d = x0 * w.x + x1 * w.y + x2 * w.z + x3 * w.w;
#pragma unroll
        for (int o = 16; o; o >>= 1) d += __shfl_xor_sync(0xffffffffu, d, o);
        if (lane == h) g_bias[h * (NRES * NRES) + pid] = d;
    }
}

// ===================== SGEMM body (M=32768, K=256, N=256) =====================
// 128x64 block tile, 256 threads, 8x4 per thread, K-step 16.
// MODE: 0 plain, 1 scale, 2 sigmoid(x+eb[col]), 3 x+eb[col]
template <int MODE>
__device__ __forceinline__ void gemm_body(
    const float* __restrict__ A, const float* __restrict__ B,
    float* __restrict__ C, const float* __restrict__ eb, float scale,
    float (*As)[128], float (*Bs)[68])
{
    int tid = threadIdx.x;
    int tx = tid & 15, ty = tid >> 4;
    int m0 = blockIdx.y * 128, n0 = blockIdx.x * 64;

    float acc[8][4];
#pragma unroll
    for (int i = 0; i < 8; i++)
#pragma unroll
        for (int j = 0; j < 4; j++) acc[i][j] = 0.f;

    for (int k0 = 0; k0 < 256; k0 += 16) {
#pragma unroll
        for (int i = 0; i < 2; i++) {
            int f = tid + i * 256;
            int ar = f >> 2, ac = (f & 3) << 2;
            const float4 v = *(const float4*)(A + (m0 + ar) * 256 + k0 + ac);
            As[ac + 0][ar] = v.x; As[ac + 1][ar] = v.y;
            As[ac + 2][ar] = v.z; As[ac + 3][ar] = v.w;
        }
        {
            int br = tid >> 4, bc = (tid & 15) << 2;
            *(float4*)&Bs[br][bc] = *(const float4*)(B + (k0 + br) * 256 + n0 + bc);
        }
        __syncthreads();
#pragma unroll
        for (int kk = 0; kk < 16; kk++) {
            float4 a0 = *(float4*)&As[kk][ty * 8];
            float4 a1 = *(float4*)&As[kk][ty * 8 + 4];
            float4 bv = *(float4*)&Bs[kk][tx * 4];
            float a[8] = {a0.x, a0.y, a0.z, a0.w, a1.x, a1.y, a1.z, a1.w};
            float b[4] = {bv.x, bv.y, bv.z, bv.w};
#pragma unroll
            for (int i = 0; i < 8; i++)
#pragma unroll
                for (int j = 0; j < 4; j++) acc[i][j] += a[i] * b[j];
        }
        __syncthreads();
    }

#pragma unroll
    for (int i = 0; i < 8; i++) {
        int row = m0 + ty * 8 + i;
        float o[4];
#pragma unroll
        for (int j = 0; j < 4; j++) {
            float t = acc[i][j];
            int col = n0 + tx * 4 + j;
            if (MODE == 1) t *= scale;
            else if (MODE == 2) t = 1.f / (1.f + __expf(-(t + eb[col])));
            else if (MODE == 3) t += eb[col];
            o[j] = t;
        }
        *(float4*)(C + row * 256 + n0 + tx * 4) =
            make_float4(o[0], o[1], o[2], o[3]);
    }
}

// ===================== 3) QKVG projections =====================
__global__ __launch_bounds__(256) void proj_kernel(
    const float* __restrict__ Bq, const float* __restrict__ Bk,
    const float* __restrict__ Bv, const float* __restrict__ Bg,
    const float* __restrict__ gb)
{
    __shared__ float As[16][128];
    __shared__ float Bs[16][68];
    int z = blockIdx.z;
    if (z == 0)      gemm_body<1>(g_x, Bq, g_q, nullptr, 0.17677669529663687f, As, Bs);
    else if (z == 1) gemm_body<0>(g_x, Bk, g_k, nullptr, 0.f, As, Bs);
    else if (z == 2) gemm_body<0>(g_x, Bv, g_v, nullptr, 0.f, As, Bs);
    else             gemm_body<2>(g_x, Bg, g_g, gb, 0.f, As, Bs);
}

// ===================== 5) output projection =====================
__global__ __launch_bounds__(256) void out_kernel(
    const float* __restrict__ ow, const float* __restrict__ ob,
    float* __restrict__ out)
{
    __shared__ float As[16][128];
    __shared__ float Bs[16][68];
    gemm_body<3>(g_wg, ow, out, ob, 0.f, As, Bs);
}

// ===================== 4) attention per (b,h) =====================
// smem: Qs[256][32], Kt[32][257], Vs[256][33], Ps[8][256], Mb[256]
#define ATTN_SMEM_FLOATS (8192 + 32 * 257 + 256 * 33 + 2048 + 256)
__global__ __launch_bounds__(256) void attn_kernel(const float* __restrict__ mask)
{
    int bh = blockIdx.x;
    int b = bh >> 3, h = bh & 7;
    extern __shared__ float sm[];
    float* Qs = sm;                    // [256][32]
    float* Kt = Qs + 8192;             // [32][257]  (c-major, padded)
    float* Vs = Kt + 32 * 257;         // [256][33]
    float* Ps = Vs + 256 * 33;         // [8 warps][256]
    float* Mb = Ps + 2048;             // [256]

    int tid = threadIdx.x;
    for (int i = tid; i < 8192; i += 256) {
        int r = i >> 5, c = i & 31;
        int gi = (b * 256 + r) * 256 + h * 32 + c;
        Qs[i] = g_q[gi];
        Kt[c * 257 + r] = g_k[gi];
        Vs[r * 33 + c] = g_v[gi];
    }
    Mb[tid] = 1e9f * (mask[b * 256 + tid] - 1.0f);
    __syncthreads();

    int w = tid >> 5, lane = tid & 31;
    float* Pw = Ps + w * 256;

    for (int rr = 0; rr < 32; rr += 4) {
        int q0 = w * 32 + rr;
        float l[4][8];
#pragma unroll
        for (int r = 0; r < 4; r++) {
            const float* brow = g_bias + (h * 256 + q0 + r) * 256;
#pragma unroll
            for (int j = 0; j < 8; j++) {
                int k = lane + 32 * j;
                l[r][j] = Mb[k] + brow[k];
            }
        }
#pragma unroll
        for (int c = 0; c < 32; c++) {
            float q0v = Qs[(q0 + 0) * 32 + c];
            float q1v = Qs[(q0 + 1) * 32 + c];
            float q2v = Qs[(q0 + 2) * 32 + c];
            float q3v = Qs[(q0 + 3) * 32 + c];
            const float* kr = Kt + c * 257 + lane;
#pragma unroll
            for (int j = 0; j < 8; j++) {
                float kv = kr[32 * j];
                l[0][j] += q0v * kv;
                l[1][j] += q1v * kv;
                l[2][j] += q2v * kv;
                l[3][j] += q3v * kv;
            }
        }
        // per-row softmax + PV
        for (int r = 0; r < 4; r++) {
            float m = l[r][0];
#pragma unroll
            for (int j = 1; j < 8; j++) m = fmaxf(m, l[r][j]);
#pragma unroll
            for (int o = 16; o; o >>= 1)
                m = fmaxf(m, __shfl_xor_sync(0xffffffffu, m, o));
            float s = 0.f;
#pragma unroll
            for (int j = 0; j < 8; j++) { l[r][j] = __expf(l[r][j] - m); s += l[r][j]; }
#pragma unroll
            for (int o = 16; o; o >>= 1) s += __shfl_xor_sync(0xffffffffu, s, o);
            float inv = 1.f / s;
#pragma unroll
            for (int j = 0; j < 8; j++) Pw[lane + 32 * j] = l[r][j] * inv;
            __syncwarp();
            float o = 0.f;
#pragma unroll 8
            for (int k = 0; k < 256; k++) o += Pw[k] * Vs[k * 33 + lane];
            int gi = (b * 256 + q0 + r) * 256 + h * 32 + lane;
            g_wg[gi] = o * g_g[gi];
            __syncwarp();
        }
    }
}

// ===================== launcher =====================
extern "C" void kernel_launch(void* const* d_in, const int* in_sizes, int n_in,
                              void* d_out, int out_size)
{
    const float* msa   = (const float*)d_in[0];
    const float* mask  = (const float*)d_in[1];
    const float* pair  = (const float*)d_in[2];
    const float* qn_s  = (const float*)d_in[3];
    const float* qn_b  = (const float*)d_in[4];
    const float* pn_s  = (const float*)d_in[5];
    const float* pn_b  = (const float*)d_in[6];
    const float* f2w   = (const float*)d_in[7];
    const float* q_w   = (const float*)d_in[8];
    const float* k_w   = (const float*)d_in[9];
    const float* v_w   = (const float*)d_in[10];
    const float* g_wt  = (const float*)d_in[11];
    const float* g_b   = (const float*)d_in[12];
    const float* o_w   = (const float*)d_in[13];
    const float* o_b   = (const float*)d_in[14];
    float* out = (float*)d_out;

    cudaFuncSetAttribute(attn_kernel, cudaFuncAttributeMaxDynamicSharedMemorySize,
                         ATTN_SMEM_FLOATS * (int)sizeof(float));

    ln_msa_kernel<<<NROWS, 256>>>(msa, qn_s, qn_b);
    pair_bias_kernel<<<(NRES * NRES) / 8, 256>>>(pair, pn_s, pn_b, f2w);
    proj_kernel<<<dim3(4, 256, 4), 256>>>(q_w, k_w, v_w, g_wt, g_b);
    attn_kernel<<<NSEQ * NHEAD, 256, ATTN_SMEM_FLOATS * (int)sizeof(float)>>>(mask);
    out_kernel<<<dim3(4, 256, 1), 256>>>(o_w, o_b, out);
}

// round 7
// speedup vs baseline: 1.1392x; 1.1392x over previous
#include <cuda_runtime.h>
#include <math.h>

#define NSEQ 128
#define NRES 256
#define MSA_DIM 256
#define PAIR_DIM 128
#define NHEAD 8
#define HEAD_DIM 32
#define NROWS (NSEQ * NRES) /* 32768 */

// -------- scratch (device globals; no allocations allowed) --------
__device__ float g_x[NROWS * MSA_DIM];     // LN(msa_act)
__device__ float g_q[NROWS * MSA_DIM];     // q (scaled)
__device__ float g_k[NROWS * MSA_DIM];
__device__ float g_v[NROWS * MSA_DIM];
__device__ float g_g[NROWS * MSA_DIM];     // sigmoid gate
__device__ float g_wg[NROWS * MSA_DIM];    // weighted_avg * gate
__device__ float g_bias[NHEAD * NRES * NRES]; // nonbatched bias [h][q][k]

// ===================== 1) LayerNorm of msa_act =====================
__global__ __launch_bounds__(256) void ln_msa_kernel(
    const float* __restrict__ msa, const float* __restrict__ sc,
    const float* __restrict__ bi)
{
    int row = blockIdx.x;
    int t = threadIdx.x;
    float v = msa[row * 256 + t];
    float s = v, s2 = v * v;
#pragma unroll
    for (int o = 16; o; o >>= 1) {
        s  += __shfl_xor_sync(0xffffffffu, s, o);
        s2 += __shfl_xor_sync(0xffffffffu, s2, o);
    }
    __shared__ float ss[8], ss2[8];
    if ((t & 31) == 0) { ss[t >> 5] = s; ss2[t >> 5] = s2; }
    __syncthreads();
    float tot = 0.f, tot2 = 0.f;
#pragma unroll
    for (int i = 0; i < 8; i++) { tot += ss[i]; tot2 += ss2[i]; }
    float mu  = tot * (1.f / 256.f);
    float var = tot2 * (1.f / 256.f) - mu * mu;
    float r = rsqrtf(var + 1e-5f);
    g_x[row * 256 + t] = (v - mu) * r * sc[t] + bi[t];
}

// ===================== 2) pair LN + feat2d projection =====================
__global__ __launch_bounds__(256) void pair_bias_kernel(
    const float* __restrict__ pair, const float* __restrict__ psc,
    const float* __restrict__ pbi, const float* __restrict__ f2w)
{
    __shared__ float f2t[NHEAD * PAIR_DIM]; // transposed: [h][c]
    int tid = threadIdx.x;
    for (int i = tid; i < NHEAD * PAIR_DIM; i += 256) {
        int c = i >> 3, h = i & 7;
        f2t[h * PAIR_DIM + c] = f2w[i];
    }
    __syncthreads();

    int pid = blockIdx.x * 8 + (tid >> 5); // pair index q*256+k
    int lane = tid & 31;

    const float* row = pair + pid * PAIR_DIM;
    float4 v = *(const float4*)(row + lane * 4);
    float s = v.x + v.y + v.z + v.w;
    float s2 = v.x * v.x + v.y * v.y + v.z * v.z + v.w * v.w;
#pragma unroll
    for (int o = 16; o; o >>= 1) {
        s  += __shfl_xor_sync(0xffffffffu, s, o);
        s2 += __shfl_xor_sync(0xffffffffu, s2, o);
    }
    float mu  = s * (1.f / 128.f);
    float var = s2 * (1.f / 128.f) - mu * mu;
    float r = rsqrtf(var + 1e-5f);

    float4 sc = *(const float4*)(psc + lane * 4);
    float4 bb = *(const float4*)(pbi + lane * 4);
    float x0 = (v.x - mu) * r * sc.x + bb.x;
    float x1 = (v.y - mu) * r * sc.y + bb.y;
    float x2 = (v.z - mu) * r * sc.z + bb.z;
    float x3 = (v.w - mu) * r * sc.w + bb.w;

#pragma unroll
    for (int h = 0; h < 8; h++) {
        const float4 w = *(const float4*)&f2t[h * PAIR_DIM + lane * 4];
        float d = x0 * w.x + x1 * w.y + x2 * w.z + x3 * w.w;
#pragma unroll
        for (int o = 16; o; o >>= 1) d += __shfl_xor_sync(0xffffffffu, d, o);
        if (lane == h) g_bias[h * (NRES * NRES) + pid] = d;
    }
}

// ===================== SGEMM body (M=32768, K=256, N=256) =====================
// MODE: 0 plain, 1 scale, 2 sigmoid(x+eb[col]), 3 x+eb[col]
template <int MODE>
__device__ __forceinline__ void gemm_body(
    const float* __restrict__ A, const float* __restrict__ B,
    float* __restrict__ C, const float* __restrict__ eb, float scale,
    float (*As)[128], float (*Bs)[68])
{
    int tid = threadIdx.x;
    int tx = tid & 15, ty = tid >> 4;
    int m0 = blockIdx.y * 128, n0 = blockIdx.x * 64;

    float acc[8][4];
#pragma unroll
    for (int i = 0; i < 8; i++)
#pragma unroll
        for (int j = 0; j < 4; j++) acc[i][j] = 0.f;

    for (int k0 = 0; k0 < 256; k0 += 16) {
#pragma unroll
        for (int i = 0; i < 2; i++) {
            int f = tid + i * 256;
            int ar = f >> 2, ac = (f & 3) << 2;
            const float4 v = *(const float4*)(A + (m0 + ar) * 256 + k0 + ac);
            As[ac + 0][ar] = v.x; As[ac + 1][ar] = v.y;
            As[ac + 2][ar] = v.z; As[ac + 3][ar] = v.w;
        }
        {
            int br = tid >> 4, bc = (tid & 15) << 2;
            *(float4*)&Bs[br][bc] = *(const float4*)(B + (k0 + br) * 256 + n0 + bc);
        }
        __syncthreads();
#pragma unroll
        for (int kk = 0; kk < 16; kk++) {
            float4 a0 = *(float4*)&As[kk][ty * 8];
            float4 a1 = *(float4*)&As[kk][ty * 8 + 4];
            float4 bv = *(float4*)&Bs[kk][tx * 4];
            float a[8] = {a0.x, a0.y, a0.z, a0.w, a1.x, a1.y, a1.z, a1.w};
            float b[4] = {bv.x, bv.y, bv.z, bv.w};
#pragma unroll
            for (int i = 0; i < 8; i++)
#pragma unroll
                for (int j = 0; j < 4; j++) acc[i][j] += a[i] * b[j];
        }
        __syncthreads();
    }

#pragma unroll
    for (int i = 0; i < 8; i++) {
        int row = m0 + ty * 8 + i;
        float o[4];
#pragma unroll
        for (int j = 0; j < 4; j++) {
            float t = acc[i][j];
            int col = n0 + tx * 4 + j;
            if (MODE == 1) t *= scale;
            else if (MODE == 2) t = 1.f / (1.f + __expf(-(t + eb[col])));
            else if (MODE == 3) t += eb[col];
            o[j] = t;
        }
        *(float4*)(C + row * 256 + n0 + tx * 4) =
            make_float4(o[0], o[1], o[2], o[3]);
    }
}

// ===================== 3) QKVG projections =====================
__global__ __launch_bounds__(256) void proj_kernel(
    const float* __restrict__ Bq, const float* __restrict__ Bk,
    const float* __restrict__ Bv, const float* __restrict__ Bg,
    const float* __restrict__ gb)
{
    __shared__ float As[16][128];
    __shared__ float Bs[16][68];
    int z = blockIdx.z;
    if (z == 0)      gemm_body<1>(g_x, Bq, g_q, nullptr, 0.17677669529663687f, As, Bs);
    else if (z == 1) gemm_body<0>(g_x, Bk, g_k, nullptr, 0.f, As, Bs);
    else if (z == 2) gemm_body<0>(g_x, Bv, g_v, nullptr, 0.f, As, Bs);
    else             gemm_body<2>(g_x, Bg, g_g, gb, 0.f, As, Bs);
}

// ===================== 5) output projection =====================
__global__ __launch_bounds__(256) void out_kernel(
    const float* __restrict__ ow, const float* __restrict__ ob,
    float* __restrict__ out)
{
    __shared__ float As[16][128];
    __shared__ float Bs[16][68];
    gemm_body<3>(g_wg, ow, out, ob, 0.f, As, Bs);
}

// ===================== 4) attention per (b,h), float4 smem version =========
// smem floats:
//   Qs[256][32]   broadcast reads            8192
//   Ks[256][36]   float4 reads, stride 36    9216
//   Vt[32][260]   col-major, stride 260      8320
//   Ps[16w][4][256]                          16384
//   Mb[256]                                  256
#define SM_QS 0
#define SM_KS 8192
#define SM_VT (8192 + 9216)
#define SM_PS (8192 + 9216 + 8320)
#define SM_MB (8192 + 9216 + 8320 + 16384)
#define ATTN_SMEM_FLOATS (8192 + 9216 + 8320 + 16384 + 256)

__global__ __launch_bounds__(512) void attn_kernel(const float* __restrict__ mask)
{
    int bh = blockIdx.x;
    int b = bh >> 3, h = bh & 7;
    extern __shared__ float sm[];
    float* Qs = sm + SM_QS;
    float* Ks = sm + SM_KS;
    float* Vt = sm + SM_VT;
    float* Ps = sm + SM_PS;
    float* Mb = sm + SM_MB;

    int tid = threadIdx.x;
    const int gbase = b * 256 * 256 + h * 32;

    // load Q (stride 32) and K (stride 36), float4 coalesced
    for (int i = tid; i < 2048; i += 512) {
        int row = i >> 3, c4 = i & 7;
        int ga = gbase + row * 256 + c4 * 4;
        float4 qv = *(const float4*)(g_q + ga);
        *(float4*)&Qs[row * 32 + c4 * 4] = qv;
        float4 kv = *(const float4*)(g_k + ga);
        *(float4*)&Ks[row * 36 + c4 * 4] = kv;
    }
    // load V transposed: Vt[col][k], stride 260 (coalesced gmem reads)
    for (int i = tid; i < 2048; i += 512) {
        int k = i >> 3, c4 = i & 7;
        float4 vv = *(const float4*)(g_v + gbase + k * 256 + c4 * 4);
        Vt[(c4 * 4 + 0) * 260 + k] = vv.x;
        Vt[(c4 * 4 + 1) * 260 + k] = vv.y;
        Vt[(c4 * 4 + 2) * 260 + k] = vv.z;
        Vt[(c4 * 4 + 3) * 260 + k] = vv.w;
    }
    if (tid < 256) Mb[tid] = 1e9f * (mask[b * 256 + tid] - 1.0f);
    __syncthreads();

    int w = tid >> 5, lane = tid & 31;
    float* Pw = Ps + w * 4 * 256;

    for (int pass = 0; pass < 2; pass++) {
        int q0 = w * 16 + pass * 8;
        float acc[8][8];
#pragma unroll
        for (int r = 0; r < 8; r++) {
            const float* brow = g_bias + (h * 256 + q0 + r) * 256;
#pragma unroll
            for (int j = 0; j < 8; j++) {
                int k = lane + 32 * j;
                acc[r][j] = Mb[k] + brow[k];
            }
        }
        // QK^T with float4 over head dim
#pragma unroll
        for (int c4 = 0; c4 < 8; c4++) {
#pragma unroll
            for (int jh = 0; jh < 2; jh++) {
                float4 kq[4];
#pragma unroll
                for (int j = 0; j < 4; j++)
                    kq[j] = *(const float4*)&Ks[(lane + 32 * (jh * 4 + j)) * 36 + c4 * 4];
#pragma unroll
                for (int r = 0; r < 8; r++) {
                    float4 q4 = *(const float4*)&Qs[(q0 + r) * 32 + c4 * 4];
#pragma unroll
                    for (int j = 0; j < 4; j++) {
                        acc[r][jh * 4 + j] += q4.x * kq[j].x + q4.y * kq[j].y
                                            + q4.z * kq[j].z + q4.w * kq[j].w;
                    }
                }
            }
        }
        // softmax + PV, 4 rows at a time
#pragma unroll
        for (int grp = 0; grp < 2; grp++) {
#pragma unroll
            for (int r4 = 0; r4 < 4; r4++) {
                int r = grp * 4 + r4;
                float m = acc[r][0];
#pragma unroll
                for (int j = 1; j < 8; j++) m = fmaxf(m, acc[r][j]);
#pragma unroll
                for (int o = 16; o; o >>= 1)
                    m = fmaxf(m, __shfl_xor_sync(0xffffffffu, m, o));
                float s = 0.f;
#pragma unroll
                for (int j = 0; j < 8; j++) {
                    float e = __expf(acc[r][j] - m);
                    acc[r][j] = e; s += e;
                }
#pragma unroll
                for (int o = 16; o; o >>= 1) s += __shfl_xor_sync(0xffffffffu, s, o);
                float inv = 1.f / s;
#pragma unroll
                for (int j = 0; j < 8; j++)
                    Pw[r4 * 256 + lane + 32 * j] = acc[r][j] * inv;
            }
            __syncwarp();
            float ov[4] = {0.f, 0.f, 0.f, 0.f};
            const float* vrow = Vt + lane * 260;
#pragma unroll 8
            for (int kk = 0; kk < 256; kk += 4) {
                float4 v4 = *(const float4*)(vrow + kk);
                float4 p0 = *(const float4*)&Pw[0 * 256 + kk];
                float4 p1 = *(const float4*)&Pw[1 * 256 + kk];
                float4 p2 = *(const float4*)&Pw[2 * 256 + kk];
                float4 p3 = *(const float4*)&Pw[3 * 256 + kk];
                ov[0] += p0.x * v4.x + p0.y * v4.y + p0.z * v4.z + p0.w * v4.w;
                ov[1] += p1.x * v4.x + p1.y * v4.y + p1.z * v4.z + p1.w * v4.w;
                ov[2] += p2.x * v4.x + p2.y * v4.y + p2.z * v4.z + p2.w * v4.w;
                ov[3] += p3.x * v4.x + p3.y * v4.y + p3.z * v4.z + p3.w * v4.w;
            }
#pragma unroll
            for (int r4 = 0; r4 < 4; r4++) {
                int gi = gbase + (q0 + grp * 4 + r4) * 256 + lane;
                g_wg[gi] = ov[r4] * g_g[gi];
            }
            __syncwarp();
        }
    }
}

// ===================== launcher =====================
extern "C" void kernel_launch(void* const* d_in, const int* in_sizes, int n_in,
                              void* d_out, int out_size)
{
    const float* msa   = (const float*)d_in[0];
    const float* mask  = (const float*)d_in[1];
    const float* pair  = (const float*)d_in[2];
    const float* qn_s  = (const float*)d_in[3];
    const float* qn_b  = (const float*)d_in[4];
    const float* pn_s  = (const float*)d_in[5];
    const float* pn_b  = (const float*)d_in[6];
    const float* f2w   = (const float*)d_in[7];
    const float* q_w   = (const float*)d_in[8];
    const float* k_w   = (const float*)d_in[9];
    const float* v_w   = (const float*)d_in[10];
    const float* g_wt  = (const float*)d_in[11];
    const float* g_b   = (const float*)d_in[12];
    const float* o_w   = (const float*)d_in[13];
    const float* o_b   = (const float*)d_in[14];
    float* out = (float*)d_out;

    cudaFuncSetAttribute(attn_kernel, cudaFuncAttributeMaxDynamicSharedMemorySize,
                         ATTN_SMEM_FLOATS * (int)sizeof(float));

    ln_msa_kernel<<<NROWS, 256>>>(msa, qn_s, qn_b);
    pair_bias_kernel<<<(NRES * NRES) / 8, 256>>>(pair, pn_s, pn_b, f2w);
    proj_kernel<<<dim3(4, 256, 4), 256>>>(q_w, k_w, v_w, g_wt, g_b);
    attn_kernel<<<NSEQ * NHEAD, 512, ATTN_SMEM_FLOATS * (int)sizeof(float)>>>(mask);
    out_kernel<<<dim3(4, 256, 1), 256>>>(o_w, o_b, out);
}